// round 1
// baseline (speedup 1.0000x reference)
#include <cuda_runtime.h>

// Problem constants
constexpr int Bb  = 2;
constexpr int Ss  = 2048;
constexpr int Dd  = 1024;
constexpr int Hh  = 16;
constexpr int HDd = 64;

// Scratch (allocation-free: __device__ globals)
__device__ float g_q[Bb * Hh * Ss * HDd];    // [B,H,S,HD]
__device__ float g_k[Bb * Hh * Ss * HDd];
__device__ float g_v[Bb * Hh * Ss * HDd];
__device__ float g_ctx[Bb * Ss * Dd];        // [B,S,D]

// ---------------------------------------------------------------------------
// 128x128x8 register-tiled SGEMM body. M=4096, N=1024, K=1024 fixed.
// HEADED: B matrix is W[H,D,HD] viewed as [K=D, N=H*HD]
// SCATTER: output goes to [B,H,S,HD] layout instead of row-major [M,N]
// ---------------------------------------------------------------------------
template<bool HEADED, bool SCATTER>
__device__ __forceinline__ void gemm_body(
    const float* __restrict__ A, const float* __restrict__ W,
    const float* __restrict__ bias, float* __restrict__ C,
    int m0, int n0)
{
    __shared__ float As[8][132];   // transposed A tile [k][m], padded
    __shared__ float Bs[8][128];   // B tile [k][n]

    const int t  = threadIdx.x;    // 0..255
    const int tx = t & 15;
    const int ty = t >> 4;

    float acc[8][8];
#pragma unroll
    for (int i = 0; i < 8; i++)
#pragma unroll
        for (int j = 0; j < 8; j++) acc[i][j] = 0.0f;

    const int a_row = t >> 1;          // 0..127
    const int a_k4  = (t & 1) << 2;    // 0 or 4
    const int b_k   = t >> 5;          // 0..7
    const int b_c   = (t & 31) << 2;   // 0..124

    for (int k0 = 0; k0 < Dd; k0 += 8) {
        // A tile: 128 rows x 8 k, transposed store
        float4 av = *(const float4*)(A + (m0 + a_row) * Dd + k0 + a_k4);
        As[a_k4 + 0][a_row] = av.x;
        As[a_k4 + 1][a_row] = av.y;
        As[a_k4 + 2][a_row] = av.z;
        As[a_k4 + 3][a_row] = av.w;
        // B tile: 8 k x 128 n
        const int n = n0 + b_c;
        const float* bp = HEADED
            ? (W + ((n >> 6) << 16) + (k0 + b_k) * HDd + (n & 63))
            : (W + (k0 + b_k) * 1024 + n);
        *(float4*)&Bs[b_k][b_c] = *(const float4*)bp;
        __syncthreads();

#pragma unroll
        for (int kk = 0; kk < 8; kk++) {
            float a[8], b[8];
            *(float4*)&a[0] = *(const float4*)&As[kk][(ty << 2)];
            *(float4*)&a[4] = *(const float4*)&As[kk][64 + (ty << 2)];
            *(float4*)&b[0] = *(const float4*)&Bs[kk][(tx << 2)];
            *(float4*)&b[4] = *(const float4*)&Bs[kk][64 + (tx << 2)];
#pragma unroll
            for (int i = 0; i < 8; i++)
#pragma unroll
                for (int j = 0; j < 8; j++)
                    acc[i][j] += a[i] * b[j];
        }
        __syncthreads();
    }

    // Epilogue: bias add + store
#pragma unroll
    for (int ih = 0; ih < 2; ih++)
#pragma unroll
    for (int ii = 0; ii < 4; ii++) {
        const int i = ih * 4 + ii;
        const int m = m0 + ih * 64 + (ty << 2) + ii;
#pragma unroll
        for (int jh = 0; jh < 2; jh++) {
            const int n = n0 + jh * 64 + (tx << 2);
            float4 r;
            r.x = acc[i][jh * 4 + 0] + bias[n + 0];
            r.y = acc[i][jh * 4 + 1] + bias[n + 1];
            r.z = acc[i][jh * 4 + 2] + bias[n + 2];
            r.w = acc[i][jh * 4 + 3] + bias[n + 3];
            if (SCATTER) {
                const int bb = m >> 11, s = m & 2047;
                const int h  = n >> 6,  kk2 = n & 63;
                *(float4*)(C + ((((bb << 4) + h) * Ss + s) << 6) + kk2) = r;
            } else {
                *(float4*)(C + m * Dd + n) = r;
            }
        }
    }
}

// QKV projection: grid (N/128=8, M/128=32, z=3)
__global__ __launch_bounds__(256)
void qkv_kernel(const float* __restrict__ q, const float* __restrict__ k,
                const float* __restrict__ v,
                const float* __restrict__ Wq, const float* __restrict__ Wk,
                const float* __restrict__ Wv,
                const float* __restrict__ bq, const float* __restrict__ bk,
                const float* __restrict__ bv)
{
    const int z = blockIdx.z;
    const float* A  = (z == 0) ? q  : (z == 1) ? k  : v;
    const float* W  = (z == 0) ? Wq : (z == 1) ? Wk : Wv;
    const float* bi = (z == 0) ? bq : (z == 1) ? bk : bv;
    float* C        = (z == 0) ? g_q : (z == 1) ? g_k : g_v;
    gemm_body<true, true>(A, W, bi, C, blockIdx.y * 128, blockIdx.x * 128);
}

// Output projection: grid (8, 32)
__global__ __launch_bounds__(256)
void oproj_kernel(const float* __restrict__ Wo, const float* __restrict__ bo,
                  float* __restrict__ out)
{
    gemm_body<false, false>(g_ctx, Wo, bo, out, blockIdx.y * 128, blockIdx.x * 128);
}

// ---------------------------------------------------------------------------
// Flash attention: BM=64 Q rows per block, BN=64 KV tile, HD=64.
// 256 threads as 16x16; each thread owns a 4x4 of the score tile and a 4x4 of O.
// Shared: Qs [kk][r] (stride 68), Ks [kk][j] (stride 68, reused as Ps [j][r]),
// Vs [j][c] (stride 64). Total 51200 B dynamic.
// ---------------------------------------------------------------------------
constexpr int ATT_SMEM = (2 * 64 * 68 + 64 * 64) * 4;

__global__ __launch_bounds__(256)
void attn_kernel()
{
    extern __shared__ float sm[];
    float* Qs   = sm;               // 64*68
    float* KsPs = sm + 64 * 68;     // 64*68
    float* Vs   = sm + 2 * 64 * 68; // 64*64

    const int t  = threadIdx.x;
    const int tx = t & 15;
    const int ty = t >> 4;
    const int bh = blockIdx.y;            // b*16 + h
    const int q0 = blockIdx.x * 64;
    const float scale = 0.125f;           // 1/sqrt(64)

    const float* Qg = g_q + (bh * Ss + q0) * HDd;
    const float* Kg = g_k + bh * Ss * HDd;
    const float* Vg = g_v + bh * Ss * HDd;

    // Load Q tile transposed with scale folded in
    for (int i = t; i < 64 * 64; i += 256) {
        const int kk = i & 63, r = i >> 6;
        Qs[kk * 68 + r] = Qg[i] * scale;
    }

    float m[4], l[4], o[4][4];
#pragma unroll
    for (int i = 0; i < 4; i++) {
        m[i] = -1e30f;
        l[i] = 0.0f;
#pragma unroll
        for (int j = 0; j < 4; j++) o[i][j] = 0.0f;
    }

    for (int jt = 0; jt < Ss; jt += 64) {
        __syncthreads();  // previous PV done (and first-iter Q load visible)

        // K tile transposed, V tile direct
        const float* Kg2 = Kg + jt * 64;
        for (int i = t; i < 64 * 64; i += 256) {
            const int kk = i & 63, j = i >> 6;
            KsPs[kk * 68 + j] = Kg2[i];
        }
        const float* Vg2 = Vg + jt * 64;
        for (int i = t; i < 1024; i += 256)
            *(float4*)&Vs[i * 4] = *(const float4*)&Vg2[i * 4];
        __syncthreads();

        // Scores: s[i][j] = (scaled q_r) . k_c
        float s[4][4];
#pragma unroll
        for (int i = 0; i < 4; i++)
#pragma unroll
            for (int j = 0; j < 4; j++) s[i][j] = 0.0f;

#pragma unroll 8
        for (int kk = 0; kk < 64; kk++) {
            float4 a = *(const float4*)&Qs[kk * 68 + (ty << 2)];
            float4 b = *(const float4*)&KsPs[kk * 68 + (tx << 2)];
            float av[4] = {a.x, a.y, a.z, a.w};
            float bv[4] = {b.x, b.y, b.z, b.w};
#pragma unroll
            for (int i = 0; i < 4; i++)
#pragma unroll
                for (int j = 0; j < 4; j++)
                    s[i][j] += av[i] * bv[j];
        }

        // Online softmax (row stats reduced across the 16 tx lanes)
#pragma unroll
        for (int i = 0; i < 4; i++) {
            float rm = fmaxf(fmaxf(s[i][0], s[i][1]), fmaxf(s[i][2], s[i][3]));
#pragma unroll
            for (int off = 8; off >= 1; off >>= 1)
                rm = fmaxf(rm, __shfl_xor_sync(0xffffffffu, rm, off));
            const float mn  = fmaxf(m[i], rm);
            const float fac = __expf(m[i] - mn);
            float rs = 0.0f;
#pragma unroll
            for (int j = 0; j < 4; j++) {
                s[i][j] = __expf(s[i][j] - mn);
                rs += s[i][j];
            }
#pragma unroll
            for (int off = 8; off >= 1; off >>= 1)
                rs += __shfl_xor_sync(0xffffffffu, rs, off);
            l[i] = l[i] * fac + rs;
            m[i] = mn;
#pragma unroll
            for (int j = 0; j < 4; j++) o[i][j] *= fac;
        }

        __syncthreads();  // all threads finished reading K tile

        // Write P transposed: Ps[j_tok][r]
#pragma unroll
        for (int j = 0; j < 4; j++)
#pragma unroll
            for (int i = 0; i < 4; i++)
                KsPs[((tx << 2) + j) * 68 + (ty << 2) + i] = s[i][j];
        __syncthreads();

        // O += P @ V
#pragma unroll 8
        for (int jj = 0; jj < 64; jj++) {
            float4 p = *(const float4*)&KsPs[jj * 68 + (ty << 2)];
            float4 v = *(const float4*)&Vs[jj * 64 + (tx << 2)];
            float pv[4] = {p.x, p.y, p.z, p.w};
            float vv[4] = {v.x, v.y, v.z, v.w};
#pragma unroll
            for (int i = 0; i < 4; i++)
#pragma unroll
                for (int j = 0; j < 4; j++)
                    o[i][j] += pv[i] * vv[j];
        }
    }

    // Normalize and write ctx [B,S,D] with D col = h*64 + c
    const int bb = bh >> 4, h = bh & 15;
#pragma unroll
    for (int i = 0; i < 4; i++) {
        const float inv = 1.0f / l[i];
        const int srow = q0 + (ty << 2) + i;
        float4 r;
        r.x = o[i][0] * inv;
        r.y = o[i][1] * inv;
        r.z = o[i][2] * inv;
        r.w = o[i][3] * inv;
        *(float4*)(g_ctx + (bb * Ss + srow) * Dd + h * 64 + (tx << 2)) = r;
    }
}

// ---------------------------------------------------------------------------
extern "C" void kernel_launch(void* const* d_in, const int* in_sizes, int n_in,
                              void* d_out, int out_size)
{
    (void)in_sizes; (void)n_in; (void)out_size;
    const float* q  = (const float*)d_in[0];
    const float* k  = (const float*)d_in[1];
    const float* v  = (const float*)d_in[2];
    const float* Wq = (const float*)d_in[3];
    const float* bq = (const float*)d_in[4];
    const float* Wk = (const float*)d_in[5];
    const float* bk = (const float*)d_in[6];
    const float* Wv = (const float*)d_in[7];
    const float* bv = (const float*)d_in[8];
    const float* Wo = (const float*)d_in[9];
    const float* bo = (const float*)d_in[10];
    float* out = (float*)d_out;

    // QKV projections: [4096,1024] x [1024,1024] x3
    dim3 gqkv(Dd / 128, (Bb * Ss) / 128, 3);
    qkv_kernel<<<gqkv, 256>>>(q, k, v, Wq, Wk, Wv, bq, bk, bv);

    // Flash attention over 32 (b,h) pairs
    cudaFuncSetAttribute(attn_kernel, cudaFuncAttributeMaxDynamicSharedMemorySize,
                         ATT_SMEM);
    attn_kernel<<<dim3(Ss / 64, Bb * Hh), 256, ATT_SMEM>>>();

    // Output projection
    oproj_kernel<<<dim3(Dd / 128, (Bb * Ss) / 128), 256>>>(Wo, bo, out);
}

// round 3
// speedup vs baseline: 1.1775x; 1.1775x over previous
#include <cuda_runtime.h>
#include <cuda_bf16.h>
#include <cstdint>

// Problem constants
constexpr int Bb  = 2;
constexpr int Ss  = 2048;
constexpr int Dd  = 1024;
constexpr int Hh  = 16;
constexpr int HDd = 64;

// ---------------------------------------------------------------------------
// Scratch (allocation-free: __device__ globals)
// ---------------------------------------------------------------------------
__device__ float g_q[Bb * Hh * Ss * HDd];    // [B,H,S,HD]
__device__ float g_k[Bb * Hh * Ss * HDd];
__device__ float g_v[Bb * Hh * Ss * HDd];
__device__ float g_ctx[Bb * Ss * Dd];        // [B,S,D]

// Split-bf16 operands, plain row-major (K contiguous).
// a_act[i]: i=0,1,2 -> q,k,v inputs; i=3 -> ctx.  [2 segs][4096][1024]
__device__ __nv_bfloat16 a_act[4][2 * 4096 * 1024];
// b_wt[i]: transposed weights as [n][k].          [2 segs][1024][1024]
__device__ __nv_bfloat16 b_wt[4][2 * 1024 * 1024];

// ---------------------------------------------------------------------------
// Helpers
// ---------------------------------------------------------------------------
__device__ __forceinline__ uint32_t smem_u32(const void* p) {
    uint32_t a;
    asm("{ .reg .u64 t; cvta.to.shared.u64 t, %1; cvt.u32.u64 %0, t; }"
        : "=r"(a) : "l"(p));
    return a;
}

#define CP16(dst, src) \
    asm volatile("cp.async.cg.shared.global [%0], [%1], 16;" :: "r"(dst), "l"(src))
#define CP_COMMIT() asm volatile("cp.async.commit_group;" ::: "memory")
#define CP_WAIT1()  asm volatile("cp.async.wait_group 1;" ::: "memory")

__device__ __forceinline__ void ldsm4(uint32_t* r, uint32_t addr) {
    asm volatile("ldmatrix.sync.aligned.m8n8.x4.shared.b16 {%0,%1,%2,%3}, [%4];"
        : "=r"(r[0]), "=r"(r[1]), "=r"(r[2]), "=r"(r[3]) : "r"(addr));
}

__device__ __forceinline__ void mma16816(float* c, const uint32_t* a, const uint32_t* b) {
    asm volatile(
        "mma.sync.aligned.m16n8k16.row.col.f32.bf16.bf16.f32 "
        "{%0,%1,%2,%3}, {%4,%5,%6,%7}, {%8,%9}, {%0,%1,%2,%3};"
        : "+f"(c[0]), "+f"(c[1]), "+f"(c[2]), "+f"(c[3])
        : "r"(a[0]), "r"(a[1]), "r"(a[2]), "r"(a[3]), "r"(b[0]), "r"(b[1]));
}

// ---------------------------------------------------------------------------
// Conversion kernels: fp32 -> hi/lo bf16 (hi = rn(x), lo = rn(x - hi))
// ---------------------------------------------------------------------------
__device__ __forceinline__ void conv8(const float* __restrict__ src,
                                      __nv_bfloat16* __restrict__ hi,
                                      __nv_bfloat16* __restrict__ lo,
                                      size_t base)
{
    float4 f0 = *(const float4*)(src + base);
    float4 f1 = *(const float4*)(src + base + 4);
    float xs[8] = {f0.x, f0.y, f0.z, f0.w, f1.x, f1.y, f1.z, f1.w};
    union { uint4 u4; __nv_bfloat16 h[8]; } H, L;
#pragma unroll
    for (int j = 0; j < 8; j++) {
        __nv_bfloat16 h = __float2bfloat16_rn(xs[j]);
        H.h[j] = h;
        L.h[j] = __float2bfloat16_rn(xs[j] - __bfloat162float(h));
    }
    *(uint4*)(hi + base) = H.u4;
    *(uint4*)(lo + base) = L.u4;
}

__global__ __launch_bounds__(256)
void conv_acts_kernel(const float* __restrict__ q, const float* __restrict__ k,
                      const float* __restrict__ v)
{
    const int z = blockIdx.z;
    const float* src = (z == 0) ? q : (z == 1) ? k : v;
    const size_t base = ((size_t)blockIdx.x * 256 + threadIdx.x) * 8;
    conv8(src, a_act[z], a_act[z] + (size_t)4096 * 1024, base);
}

__global__ __launch_bounds__(256)
void conv_ctx_kernel()
{
    const size_t base = ((size_t)blockIdx.x * 256 + threadIdx.x) * 8;
    conv8(g_ctx, a_act[3], a_act[3] + (size_t)4096 * 1024, base);
}

// Weights -> B^T [n][k], hi/lo.
__global__ __launch_bounds__(256)
void conv_w_kernel(const float* __restrict__ Wq, const float* __restrict__ Wk,
                   const float* __restrict__ Wv, const float* __restrict__ Wo)
{
    const int w = blockIdx.z;
    const float* W = (w == 0) ? Wq : (w == 1) ? Wk : (w == 2) ? Wv : Wo;
    const int k = blockIdx.x;
    __nv_bfloat16* hi = b_wt[w];
    __nv_bfloat16* lo = b_wt[w] + (size_t)1024 * 1024;
#pragma unroll
    for (int j = 0; j < 4; j++) {
        const int n = threadIdx.x * 4 + j;
        const size_t idx = (w < 3)
            ? ((size_t)(n >> 6) << 16) + (size_t)k * 64 + (n & 63)
            : (size_t)k * 1024 + n;
        const float x = W[idx];
        __nv_bfloat16 h = __float2bfloat16_rn(x);
        hi[(size_t)n * 1024 + k] = h;
        lo[(size_t)n * 1024 + k] = __float2bfloat16_rn(x - __bfloat162float(h));
    }
}

// ---------------------------------------------------------------------------
// mma.sync bf16 GEMM: CTA 128x128, 8 warps (2m x 4n), warp tile 64x32.
// K = 3 segments x 1024 (hi*hi, hi*lo, lo*hi) = 96 k32-steps.
// Double-buffered smem, cp.async, padded rows (40 bf16 = 80B) for ldmatrix.
// ---------------------------------------------------------------------------
template<bool SCATTER>
__device__ __forceinline__ void gemm_core(const __nv_bfloat16* __restrict__ At,
                                          const __nv_bfloat16* __restrict__ Bt,
                                          const float* __restrict__ bias,
                                          float* __restrict__ C,
                                          int mt, int nt)
{
    __shared__ __align__(16) __nv_bfloat16 As[2][128][40];
    __shared__ __align__(16) __nv_bfloat16 Bs[2][128][40];

    const int tid = threadIdx.x, lane = tid & 31, wid = tid >> 5;
    const int wm = wid & 1, wn = wid >> 1;    // warp grid 2(m) x 4(n)

    float acc[4][4][4] = {};

    // cp.async mapping: thread -> (row, 2 chunks of 16B)
    const int ar  = tid >> 1;              // 0..127
    const int ac0 = (tid & 1) * 2;         // 16B-chunk col: 0 or 2
    const __nv_bfloat16* Abase = At + (size_t)(mt * 128 + ar) * 1024;
    const __nv_bfloat16* Bbase = Bt + (size_t)(nt * 128 + ar) * 1024;

    const uint32_t sAs = smem_u32(As);
    const uint32_t sBs = smem_u32(Bs);
    const uint32_t dA = sAs + ar * 80 + ac0 * 16;
    const uint32_t dB = sBs + ar * 80 + ac0 * 16;

    // ldmatrix lane address components
    const uint32_t a_row = wm * 64 + (lane & 15);
    const uint32_t a_col = (lane >> 4) << 3;
    const uint32_t b_row = wn * 32 + (lane & 7) + ((lane >> 4) << 3);
    const uint32_t b_col = ((lane >> 3) & 1) << 3;

#define ISSUE(kt) do {                                                        \
    const int _kt = (kt);                                                     \
    const int _seg = _kt >> 5, _kk = _kt & 31;                                \
    const int _as = _seg >> 1, _bs = _seg & 1;                                \
    const __nv_bfloat16* _a = Abase + (size_t)_as * 4096 * 1024 + _kk * 32 + ac0 * 8; \
    const __nv_bfloat16* _b = Bbase + (size_t)_bs * 1024 * 1024 + _kk * 32 + ac0 * 8; \
    const uint32_t _da = dA + (_kt & 1) * 10240;                              \
    const uint32_t _db = dB + (_kt & 1) * 10240;                              \
    CP16(_da, _a); CP16(_da + 16, _a + 8);                                    \
    CP16(_db, _b); CP16(_db + 16, _b + 8);                                    \
    CP_COMMIT();                                                              \
} while (0)

    ISSUE(0);
    ISSUE(1);

    for (int kt = 0; kt < 96; kt++) {
        CP_WAIT1();
        __syncthreads();

        const uint32_t sa = sAs + (kt & 1) * 10240;
        const uint32_t sb = sBs + (kt & 1) * 10240;
#pragma unroll
        for (int ks = 0; ks < 32; ks += 16) {
            uint32_t af[4][4], bf[2][4];
#pragma unroll
            for (int mi = 0; mi < 4; mi++)
                ldsm4(af[mi], sa + ((a_row + mi * 16) * 40 + ks + a_col) * 2);
#pragma unroll
            for (int nj2 = 0; nj2 < 2; nj2++)
                ldsm4(bf[nj2], sb + ((b_row + nj2 * 16) * 40 + ks + b_col) * 2);
#pragma unroll
            for (int mi = 0; mi < 4; mi++)
#pragma unroll
                for (int nj = 0; nj < 4; nj++)
                    mma16816(acc[mi][nj], af[mi], &bf[nj >> 1][(nj & 1) * 2]);
        }
        __syncthreads();

        if (kt + 2 < 96) ISSUE(kt + 2);
        else CP_COMMIT();   // empty group keeps wait_group accounting aligned
    }
#undef ISSUE

    // Epilogue: bias + store (float2 per fragment row)
#pragma unroll
    for (int mi = 0; mi < 4; mi++) {
        const int r0 = mt * 128 + wm * 64 + mi * 16 + (lane >> 2);
#pragma unroll
        for (int nj = 0; nj < 4; nj++) {
            const int col = nt * 128 + wn * 32 + nj * 8 + ((lane & 3) << 1);
            const float b0 = bias[col], b1 = bias[col + 1];
            float2 v0 = {acc[mi][nj][0] + b0, acc[mi][nj][1] + b1};
            float2 v1 = {acc[mi][nj][2] + b0, acc[mi][nj][3] + b1};
            if (SCATTER) {
                const int h = col >> 6, hd = col & 63;
                const int b_0 = r0 >> 11, s0 = r0 & 2047;
                const int b_1 = (r0 + 8) >> 11, s1 = (r0 + 8) & 2047;
                *(float2*)(C + ((size_t)((b_0 * 16 + h) * 2048 + s0)) * 64 + hd) = v0;
                *(float2*)(C + ((size_t)((b_1 * 16 + h) * 2048 + s1)) * 64 + hd) = v1;
            } else {
                *(float2*)(C + (size_t)r0 * 1024 + col) = v0;
                *(float2*)(C + (size_t)(r0 + 8) * 1024 + col) = v1;
            }
        }
    }
}

__global__ __launch_bounds__(256, 2)
void qkv_gemm_kernel(const float* __restrict__ bq, const float* __restrict__ bk,
                     const float* __restrict__ bv)
{
    const int z = blockIdx.z;
    const float* bias = (z == 0) ? bq : (z == 1) ? bk : bv;
    float* C = (z == 0) ? g_q : (z == 1) ? g_k : g_v;
    gemm_core<true>(a_act[z], b_wt[z], bias, C, blockIdx.y, blockIdx.x);
}

__global__ __launch_bounds__(256, 2)
void oproj_gemm_kernel(const float* __restrict__ bo, float* __restrict__ out)
{
    gemm_core<false>(a_act[3], b_wt[3], bo, out, blockIdx.y, blockIdx.x);
}

// ---------------------------------------------------------------------------
// Flash attention (unchanged from R1, verified): BM=BN=64, 256 thr, fp32 FMA.
// ---------------------------------------------------------------------------
constexpr int ATT_SMEM = (2 * 64 * 68 + 64 * 64) * 4;

__global__ __launch_bounds__(256)
void attn_kernel()
{
    extern __shared__ float sm[];
    float* Qs   = sm;               // 64*68
    float* KsPs = sm + 64 * 68;     // 64*68
    float* Vs   = sm + 2 * 64 * 68; // 64*64

    const int t  = threadIdx.x;
    const int tx = t & 15;
    const int ty = t >> 4;
    const int bh = blockIdx.y;
    const int q0 = blockIdx.x * 64;
    const float scale = 0.125f;

    const float* Qg = g_q + (size_t)(bh * Ss + q0) * HDd;
    const float* Kg = g_k + (size_t)bh * Ss * HDd;
    const float* Vg = g_v + (size_t)bh * Ss * HDd;

    for (int i = t; i < 64 * 64; i += 256) {
        const int kk = i & 63, r = i >> 6;
        Qs[kk * 68 + r] = Qg[i] * scale;
    }

    float m[4], l[4], o[4][4];
#pragma unroll
    for (int i = 0; i < 4; i++) {
        m[i] = -1e30f; l[i] = 0.0f;
#pragma unroll
        for (int j = 0; j < 4; j++) o[i][j] = 0.0f;
    }

    for (int jt = 0; jt < Ss; jt += 64) {
        __syncthreads();
        const float* Kg2 = Kg + (size_t)jt * 64;
        for (int i = t; i < 64 * 64; i += 256) {
            const int kk = i & 63, j = i >> 6;
            KsPs[kk * 68 + j] = Kg2[i];
        }
        const float* Vg2 = Vg + (size_t)jt * 64;
        for (int i = t; i < 1024; i += 256)
            *(float4*)&Vs[i * 4] = *(const float4*)&Vg2[i * 4];
        __syncthreads();

        float s[4][4];
#pragma unroll
        for (int i = 0; i < 4; i++)
#pragma unroll
            for (int j = 0; j < 4; j++) s[i][j] = 0.0f;

#pragma unroll 8
        for (int kk = 0; kk < 64; kk++) {
            float4 a = *(const float4*)&Qs[kk * 68 + (ty << 2)];
            float4 b = *(const float4*)&KsPs[kk * 68 + (tx << 2)];
            float av[4] = {a.x, a.y, a.z, a.w};
            float bv[4] = {b.x, b.y, b.z, b.w};
#pragma unroll
            for (int i = 0; i < 4; i++)
#pragma unroll
                for (int j = 0; j < 4; j++)
                    s[i][j] += av[i] * bv[j];
        }

#pragma unroll
        for (int i = 0; i < 4; i++) {
            float rm = fmaxf(fmaxf(s[i][0], s[i][1]), fmaxf(s[i][2], s[i][3]));
#pragma unroll
            for (int off = 8; off >= 1; off >>= 1)
                rm = fmaxf(rm, __shfl_xor_sync(0xffffffffu, rm, off));
            const float mn  = fmaxf(m[i], rm);
            const float fac = __expf(m[i] - mn);
            float rs = 0.0f;
#pragma unroll
            for (int j = 0; j < 4; j++) {
                s[i][j] = __expf(s[i][j] - mn);
                rs += s[i][j];
            }
#pragma unroll
            for (int off = 8; off >= 1; off >>= 1)
                rs += __shfl_xor_sync(0xffffffffu, rs, off);
            l[i] = l[i] * fac + rs;
            m[i] = mn;
#pragma unroll
            for (int j = 0; j < 4; j++) o[i][j] *= fac;
        }

        __syncthreads();
#pragma unroll
        for (int j = 0; j < 4; j++)
#pragma unroll
            for (int i = 0; i < 4; i++)
                KsPs[((tx << 2) + j) * 68 + (ty << 2) + i] = s[i][j];
        __syncthreads();

#pragma unroll 8
        for (int jj = 0; jj < 64; jj++) {
            float4 p = *(const float4*)&KsPs[jj * 68 + (ty << 2)];
            float4 v = *(const float4*)&Vs[jj * 64 + (tx << 2)];
            float pv[4] = {p.x, p.y, p.z, p.w};
            float vv[4] = {v.x, v.y, v.z, v.w};
#pragma unroll
            for (int i = 0; i < 4; i++)
#pragma unroll
                for (int j = 0; j < 4; j++)
                    o[i][j] += pv[i] * vv[j];
        }
    }

    const int bb = bh >> 4, h = bh & 15;
#pragma unroll
    for (int i = 0; i < 4; i++) {
        const float inv = 1.0f / l[i];
        const int srow = q0 + (ty << 2) + i;
        float4 r;
        r.x = o[i][0] * inv; r.y = o[i][1] * inv;
        r.z = o[i][2] * inv; r.w = o[i][3] * inv;
        *(float4*)(g_ctx + (size_t)(bb * Ss + srow) * Dd + h * 64 + (tx << 2)) = r;
    }
}

// ---------------------------------------------------------------------------
extern "C" void kernel_launch(void* const* d_in, const int* in_sizes, int n_in,
                              void* d_out, int out_size)
{
    (void)in_sizes; (void)n_in; (void)out_size;
    const float* q  = (const float*)d_in[0];
    const float* k  = (const float*)d_in[1];
    const float* v  = (const float*)d_in[2];
    const float* Wq = (const float*)d_in[3];
    const float* bq = (const float*)d_in[4];
    const float* Wk = (const float*)d_in[5];
    const float* bk = (const float*)d_in[6];
    const float* Wv = (const float*)d_in[7];
    const float* bv = (const float*)d_in[8];
    const float* Wo = (const float*)d_in[9];
    const float* bo = (const float*)d_in[10];
    float* out = (float*)d_out;

    cudaFuncSetAttribute(attn_kernel, cudaFuncAttributeMaxDynamicSharedMemorySize,
                         ATT_SMEM);

    // Convert weights + activations to split-bf16
    conv_w_kernel<<<dim3(1024, 1, 4), 256>>>(Wq, Wk, Wv, Wo);
    conv_acts_kernel<<<dim3(2048, 1, 3), 256>>>(q, k, v);

    // QKV projections on tensor cores (M=4096, N=1024, K_eff=3072)
    qkv_gemm_kernel<<<dim3(8, 32, 3), 256>>>(bq, bk, bv);

    // Flash attention (fp32)
    attn_kernel<<<dim3(Ss / 64, Bb * Hh), 256, ATT_SMEM>>>();

    // Output projection on tensor cores
    conv_ctx_kernel<<<2048, 256>>>();
    oproj_gemm_kernel<<<dim3(8, 32), 256>>>(bo, out);
}